// round 12
// baseline (speedup 1.0000x reference)
#include <cuda_runtime.h>
#include <cuda_fp16.h>
#include <cstdint>

#define NV      500000
#define KK      27
#define MROWS   128                        // rows per conv block (4 warps x M=32)
#define NBLK    ((NV + MROWS - 1) / MROWS) // 3907 conv blocks
#define AST     72                         // A smem row stride (halves) = 144 B
#define BST     72                         // B smem row stride (halves)
#define A_BUF_H (MROWS * AST)              // 9216 halves = 18432 B per buffer
#define B_BUF_H (64 * BST)                 // 4608 halves = 9216 B per buffer
#define SMEM_TOTAL ((2 * A_BUF_H + 2 * B_BUF_H) * 2)   // 55296 B -> 4 CTAs/SM

// ---- scratch (static device globals: allocation-free per harness rules) ----
__device__ __half g_xh[(size_t)NV * 64];      // features fp16
__device__ __half g_y1h[(size_t)NV * 64];     // conv1 out / conv2 in
__device__ __half g_Wt[2][KK * 64 * 64];      // fp16 weights [k][cout][cin]
__device__ int    g_pnbr[(size_t)KK * NV];    // packed: idx if valid else -1
__device__ float  g_partials[NBLK * 128];     // per conv-block sum/sumsq
__device__ float  g_ss1[128];
__device__ float  g_ss2[128];

__device__ __forceinline__ uint32_t smem_u32(const void* p) {
    uint32_t a;
    asm("{ .reg .u64 t; cvta.to.shared.u64 t, %1; cvt.u32.u64 %0, t; }" : "=r"(a) : "l"(p));
    return a;
}
__device__ __forceinline__ void cpa16_cg(uint32_t dst, const void* src, int sz) {
    asm volatile("cp.async.cg.shared.global [%0], [%1], 16, %2;"
                 :: "r"(dst), "l"(src), "r"(sz) : "memory");
}
__device__ __forceinline__ void cpa16_ca(uint32_t dst, const void* src) {
    asm volatile("cp.async.ca.shared.global [%0], [%1], 16;"
                 :: "r"(dst), "l"(src) : "memory");
}

// ============================================================================
// Gather-GEMM submanifold conv, fp16 m16n8k16 mma.sync, fp32 accum.
// Block: 128 threads (4 warps), tile 128 rows x 64 cols; each warp M=32.
// One k-offset per stage, double-buffered cp.async, ONE __syncthreads/stage.
// Epilogue additionally emits deterministic per-block BN partials (fp32).
// ============================================================================
template <typename OutT>
__global__ __launch_bounds__(128, 4) void conv_kernel(
    const __half* __restrict__ x, const int* __restrict__ pnbr,
    const __half* __restrict__ Wt, OutT* __restrict__ y,
    float* __restrict__ partials)
{
    extern __shared__ __align__(16) __half smem[];
    const uint32_t sb = smem_u32(smem);

    const int tid  = threadIdx.x;
    const int warp = tid >> 5, lane = tid & 31;
    const int g    = lane >> 2, tig = lane & 3;     // groupID / thread-in-group
    const int rowBase = blockIdx.x * MROWS;
    const int grow = rowBase + tid;                 // one gather row per thread

    const uint32_t Ab[2] = { sb, sb + (uint32_t)A_BUF_H * 2 };
    const uint32_t Bb[2] = { sb + 4 * (uint32_t)A_BUF_H,
                             sb + 4 * (uint32_t)A_BUF_H + (uint32_t)B_BUF_H * 2 };

    float acc[16][4];
#pragma unroll
    for (int n = 0; n < 16; ++n)
#pragma unroll
        for (int j = 0; j < 4; ++j) acc[n][j] = 0.f;

    auto issue = [&](int k, int buf) {
        int pk = (grow < NV) ? pnbr[(size_t)k * NV + grow] : -1;
        const __half* srow = x + (size_t)(pk >= 0 ? pk : 0) * 64;
        int sz = (pk >= 0) ? 16 : 0;                 // zero-fill invalid rows
        uint32_t adst = Ab[buf] + (uint32_t)tid * 144;
#pragma unroll
        for (int i = 0; i < 8; ++i)
            cpa16_cg(adst + i * 16, srow + i * 8, sz);
        const __half* wsrc = Wt + (size_t)k * 4096;
#pragma unroll
        for (int i = 0; i < 4; ++i) {
            int q = tid + 128 * i;                   // 512 x 16B, 8 per 64-row
            cpa16_ca(Bb[buf] + (q >> 3) * 144 + (q & 7) * 16, wsrc + q * 8);
        }
        asm volatile("cp.async.commit_group;" ::: "memory");
    };

    issue(0, 0);

    for (int k = 0; k < KK; ++k) {
        const int buf = k & 1;
        asm volatile("cp.async.wait_group 0;" ::: "memory");   // group k done
        __syncthreads();   // publishes buf; certifies buf^1 reads finished
        if (k + 1 < KK) issue(k + 1, buf ^ 1);                 // async under MMA

        const __half* A = smem + (size_t)buf * A_BUF_H;
        const __half* B = smem + 2 * (size_t)A_BUF_H + (size_t)buf * B_BUF_H;
#pragma unroll
        for (int kc = 0; kc < 4; ++kc) {
            unsigned a[2][4];
#pragma unroll
            for (int mt = 0; mt < 2; ++mt) {
                const int r = warp * 32 + mt * 16 + g;
                a[mt][0] = *reinterpret_cast<const unsigned*>(A + r       * AST + kc * 16 + 2 * tig);
                a[mt][1] = *reinterpret_cast<const unsigned*>(A + (r + 8) * AST + kc * 16 + 2 * tig);
                a[mt][2] = *reinterpret_cast<const unsigned*>(A + r       * AST + kc * 16 + 2 * tig + 8);
                a[mt][3] = *reinterpret_cast<const unsigned*>(A + (r + 8) * AST + kc * 16 + 2 * tig + 8);
            }
#pragma unroll
            for (int n = 0; n < 8; ++n) {
                unsigned b0 = *reinterpret_cast<const unsigned*>(B + (n * 8 + g) * BST + kc * 16 + 2 * tig);
                unsigned b1 = *reinterpret_cast<const unsigned*>(B + (n * 8 + g) * BST + kc * 16 + 2 * tig + 8);
                asm volatile(
                    "mma.sync.aligned.m16n8k16.row.col.f32.f16.f16.f32 "
                    "{%0,%1,%2,%3},{%4,%5,%6,%7},{%8,%9},{%0,%1,%2,%3};\n"
                    : "+f"(acc[n][0]), "+f"(acc[n][1]), "+f"(acc[n][2]), "+f"(acc[n][3])
                    : "r"(a[0][0]), "r"(a[0][1]), "r"(a[0][2]), "r"(a[0][3]), "r"(b0), "r"(b1));
                asm volatile(
                    "mma.sync.aligned.m16n8k16.row.col.f32.f16.f16.f32 "
                    "{%0,%1,%2,%3},{%4,%5,%6,%7},{%8,%9},{%0,%1,%2,%3};\n"
                    : "+f"(acc[8 + n][0]), "+f"(acc[8 + n][1]), "+f"(acc[8 + n][2]), "+f"(acc[8 + n][3])
                    : "r"(a[1][0]), "r"(a[1][1]), "r"(a[1][2]), "r"(a[1][3]), "r"(b0), "r"(b1));
            }
        }
    }

    // ---- epilogue 1: store y (c{0,1}->row g, c{2,3}->row g+8) ----
#pragma unroll
    for (int mt = 0; mt < 2; ++mt) {
        const int r0 = rowBase + warp * 32 + mt * 16 + g;
        const int r1 = r0 + 8;
#pragma unroll
        for (int n = 0; n < 8; ++n) {
            const float* a = acc[mt * 8 + n];
            int col = n * 8 + 2 * tig;
            if constexpr (sizeof(OutT) == 4) {
                if (r0 < NV)
                    *reinterpret_cast<float2*>((float*)y + (size_t)r0 * 64 + col) = make_float2(a[0], a[1]);
                if (r1 < NV)
                    *reinterpret_cast<float2*>((float*)y + (size_t)r1 * 64 + col) = make_float2(a[2], a[3]);
            } else {
                if (r0 < NV)
                    *reinterpret_cast<__half2*>((__half*)y + (size_t)r0 * 64 + col) = __floats2half2_rn(a[0], a[1]);
                if (r1 < NV)
                    *reinterpret_cast<__half2*>((__half*)y + (size_t)r1 * 64 + col) = __floats2half2_rn(a[2], a[3]);
            }
        }
    }

    // ---- epilogue 2: deterministic per-block BN partials from fp32 accs ----
    __syncthreads();                                 // smem free for reuse
    float* smS = reinterpret_cast<float*>(smem);     // [4 warps][64]
    float* smQ = smS + 4 * 64;
#pragma unroll
    for (int n = 0; n < 8; ++n) {
        float s0 = 0.f, s1 = 0.f, q0 = 0.f, q1 = 0.f;
#pragma unroll
        for (int mt = 0; mt < 2; ++mt) {
            const int r0 = rowBase + warp * 32 + mt * 16 + g;
            const float* a = acc[mt * 8 + n];
            if (r0 < NV)     { s0 += a[0]; s1 += a[1]; q0 += a[0]*a[0]; q1 += a[1]*a[1]; }
            if (r0 + 8 < NV) { s0 += a[2]; s1 += a[3]; q0 += a[2]*a[2]; q1 += a[3]*a[3]; }
        }
#pragma unroll
        for (int d = 4; d < 32; d <<= 1) {           // reduce over g lanes
            s0 += __shfl_xor_sync(0xFFFFFFFF, s0, d);
            s1 += __shfl_xor_sync(0xFFFFFFFF, s1, d);
            q0 += __shfl_xor_sync(0xFFFFFFFF, q0, d);
            q1 += __shfl_xor_sync(0xFFFFFFFF, q1, d);
        }
        if (lane < 4) {                              // lane == tig, g == 0
            smS[warp * 64 + n * 8 + 2 * lane]     = s0;
            smS[warp * 64 + n * 8 + 2 * lane + 1] = s1;
            smQ[warp * 64 + n * 8 + 2 * lane]     = q0;
            smQ[warp * 64 + n * 8 + 2 * lane + 1] = q1;
        }
    }
    __syncthreads();
    if (tid < 64) {                                  // fixed-order combine
        float s = smS[tid] + smS[64 + tid] + smS[128 + tid] + smS[192 + tid];
        float q = smQ[tid] + smQ[64 + tid] + smQ[128 + tid] + smQ[192 + tid];
        partials[blockIdx.x * 128 + tid]      = s;
        partials[blockIdx.x * 128 + 64 + tid] = q;
    }
}

// ============================================================================
// One-shot converters / packers
// ============================================================================
__global__ __launch_bounds__(256) void cvt_features_kernel(
    const float4* __restrict__ x, __half2* __restrict__ xh)
{
    long i = (long)blockIdx.x * 256 + threadIdx.x;   // NV*16 float4s, exact
    float4 v = x[i];
    xh[2 * i]     = __floats2half2_rn(v.x, v.y);
    xh[2 * i + 1] = __floats2half2_rn(v.z, v.w);
}

__global__ void cvt_weights_kernel(
    const float* __restrict__ W1, const float* __restrict__ W2,
    __half* __restrict__ Wt)   // [2][27][cout][cin]
{
    int o = blockIdx.x * 256 + threadIdx.x;
    if (o >= 2 * KK * 4096) return;
    int wsel = o / (KK * 4096);
    int rem  = o % (KK * 4096);
    int k = rem >> 12, t = rem & 4095;
    int co = t >> 6, ci = t & 63;
    const float* W = wsel ? W2 : W1;
    Wt[o] = __float2half_rn(W[(size_t)k * 4096 + ci * 64 + co]);
}

__global__ void pack_nbr_kernel(const int* __restrict__ nbr,
                                const float* __restrict__ valid,
                                int* __restrict__ pnbr)
{
    long i = (long)blockIdx.x * 256 + threadIdx.x;
    if (i >= (long)KK * NV) return;
    pnbr[i] = (valid[i] > 0.5f) ? nbr[i] : -1;
}

// ============================================================================
// BN finalize: reduce per-block partials (fixed order -> deterministic)
// ============================================================================
__global__ void finalize_stats_kernel(
    const float* __restrict__ partials, const float* __restrict__ gamma,
    const float* __restrict__ beta, float* __restrict__ ss)
{
    const int c = threadIdx.x;   // 0..63
    float s = 0.f, q = 0.f;
    for (int b = 0; b < NBLK; ++b) {
        s += partials[b * 128 + c];
        q += partials[b * 128 + 64 + c];
    }
    const float invN = 1.0f / (float)NV;
    float mean  = s * invN;
    float var   = q * invN - mean * mean;
    float scale = gamma[c] * rsqrtf(var + 1e-5f);
    ss[c]      = scale;
    ss[64 + c] = beta[c] - mean * scale;
}

// ============================================================================
// Fused BN + ReLU (half, in place) and BN + residual + ReLU (float)
// ============================================================================
__global__ __launch_bounds__(256) void bn_act_half_kernel(
    __half2* __restrict__ y, const float* __restrict__ ss)
{
    long i = (long)blockIdx.x * 256 + threadIdx.x;   // NV*32 half2s, exact
    const int cb = (int)(i & 31);
    float2 f = __half22float2(y[i]);
    float rx = fmaf(f.x, ss[2 * cb],     ss[64 + 2 * cb]);
    float ry = fmaf(f.y, ss[2 * cb + 1], ss[64 + 2 * cb + 1]);
    y[i] = __floats2half2_rn(fmaxf(rx, 0.f), fmaxf(ry, 0.f));
}

__global__ __launch_bounds__(256) void bn_act_float_kernel(
    float* __restrict__ y, const float* __restrict__ ss,
    const float* __restrict__ residual)
{
    long i = (long)blockIdx.x * 256 + threadIdx.x;   // NV*16 float4s, exact
    float4 v = reinterpret_cast<float4*>(y)[i];
    const int cb = (int)(i & 15);
    float4 sc = reinterpret_cast<const float4*>(ss)[cb];
    float4 sh = reinterpret_cast<const float4*>(ss + 64)[cb];
    float4 f = reinterpret_cast<const float4*>(residual)[i];
    float4 r;
    r.x = fmaxf(fmaf(v.x, sc.x, sh.x) + f.x, 0.f);
    r.y = fmaxf(fmaf(v.y, sc.y, sh.y) + f.y, 0.f);
    r.z = fmaxf(fmaf(v.z, sc.z, sh.z) + f.z, 0.f);
    r.w = fmaxf(fmaf(v.w, sc.w, sh.w) + f.w, 0.f);
    reinterpret_cast<float4*>(y)[i] = r;
}

// ============================================================================
// kernel_launch
// ============================================================================
extern "C" void kernel_launch(void* const* d_in, const int* in_sizes, int n_in,
                              void* d_out, int out_size)
{
    const float* features = (const float*)d_in[0];
    const int*   nbr      = (const int*)  d_in[1];
    const float* valid    = (const float*)d_in[2];
    const float* W1       = (const float*)d_in[3];
    const float* gamma1   = (const float*)d_in[4];
    const float* beta1    = (const float*)d_in[5];
    const float* W2       = (const float*)d_in[6];
    const float* gamma2   = (const float*)d_in[7];
    const float* beta2    = (const float*)d_in[8];
    float* out = (float*)d_out;

    __half *xh, *y1h, *Wt;
    int* pnbr;
    float *partials, *ss1, *ss2;
    cudaGetSymbolAddress((void**)&xh,       g_xh);
    cudaGetSymbolAddress((void**)&y1h,      g_y1h);
    cudaGetSymbolAddress((void**)&Wt,       g_Wt);
    cudaGetSymbolAddress((void**)&pnbr,     g_pnbr);
    cudaGetSymbolAddress((void**)&partials, g_partials);
    cudaGetSymbolAddress((void**)&ss1,      g_ss1);
    cudaGetSymbolAddress((void**)&ss2,      g_ss2);

    cudaFuncSetAttribute(conv_kernel<__half>, cudaFuncAttributeMaxDynamicSharedMemorySize, SMEM_TOTAL);
    cudaFuncSetAttribute(conv_kernel<float>,  cudaFuncAttributeMaxDynamicSharedMemorySize, SMEM_TOTAL);

    const int cvtBlocks  = (int)(((long)NV * 16) / 256);       // 31250, exact
    const int bnHBlocks  = (int)(((long)NV * 32) / 256);       // 62500, exact
    const int wBlocks    = (2 * KK * 4096 + 255) / 256;
    const int pkBlocks   = (int)(((long)KK * NV + 255) / 256);

    cvt_features_kernel<<<cvtBlocks, 256>>>((const float4*)features, (__half2*)xh);
    cvt_weights_kernel<<<wBlocks, 256>>>(W1, W2, Wt);
    pack_nbr_kernel<<<pkBlocks, 256>>>(nbr, valid, pnbr);

    conv_kernel<__half><<<NBLK, 128, SMEM_TOTAL>>>(xh, pnbr, Wt, y1h, partials);
    finalize_stats_kernel<<<1, 64>>>(partials, gamma1, beta1, ss1);
    bn_act_half_kernel<<<bnHBlocks, 256>>>((__half2*)y1h, ss1);

    conv_kernel<float><<<NBLK, 128, SMEM_TOTAL>>>(y1h, pnbr, Wt + (size_t)KK * 4096, out, partials);
    finalize_stats_kernel<<<1, 64>>>(partials, gamma2, beta2, ss2);
    bn_act_float_kernel<<<cvtBlocks, 256>>>(out, ss2, features);
}

// round 15
// speedup vs baseline: 1.3637x; 1.3637x over previous
#include <cuda_runtime.h>
#include <cuda_fp16.h>
#include <cstdint>

#define NV      500000
#define KK      27
#define MROWS   128                        // rows per conv block (4 warps x M=32)
#define NBLK    ((NV + MROWS - 1) / MROWS) // 3907 conv blocks
#define AST     72                         // A smem row stride (halves) = 144 B
#define BST     72                         // B smem row stride (halves)
#define A_BUF_H (MROWS * AST)              // 9216 halves = 18432 B per buffer
#define B_BUF_H (64 * BST)                 // 4608 halves = 9216 B per buffer
#define SMEM_TOTAL ((2 * A_BUF_H + 2 * B_BUF_H) * 2)   // 55296 B -> 4 CTAs/SM

// ---- scratch (static device globals: allocation-free per harness rules) ----
__device__ __half g_xh[(size_t)NV * 64];      // features fp16
__device__ __half g_y1h[(size_t)NV * 64];     // conv1 out / conv2 in
__device__ __half g_Wt[2][KK * 64 * 64];      // fp16 weights [k][cout][cin]
__device__ int    g_pnbr[(size_t)KK * NV];    // packed: idx if valid else -1
__device__ float  g_partials[NBLK * 128];     // per conv-block sum/sumsq
__device__ float  g_ss1[128];
__device__ float  g_ss2[128];

__device__ __forceinline__ uint32_t smem_u32(const void* p) {
    uint32_t a;
    asm("{ .reg .u64 t; cvta.to.shared.u64 t, %1; cvt.u32.u64 %0, t; }" : "=r"(a) : "l"(p));
    return a;
}
__device__ __forceinline__ void cpa16_cg(uint32_t dst, const void* src, int sz) {
    asm volatile("cp.async.cg.shared.global [%0], [%1], 16, %2;"
                 :: "r"(dst), "l"(src), "r"(sz) : "memory");
}
__device__ __forceinline__ void cpa16_ca(uint32_t dst, const void* src) {
    asm volatile("cp.async.ca.shared.global [%0], [%1], 16;"
                 :: "r"(dst), "l"(src) : "memory");
}

// ============================================================================
// Gather-GEMM submanifold conv, fp16 m16n8k16 mma.sync, fp32 accum.
// Block: 128 threads (4 warps), tile 128 rows x 64 cols; each warp M=32.
// One k-offset per stage, double-buffered cp.async, ONE __syncthreads/stage.
// Epilogue additionally emits deterministic per-block BN partials (fp32).
// ============================================================================
template <typename OutT>
__global__ __launch_bounds__(128, 4) void conv_kernel(
    const __half* __restrict__ x, const int* __restrict__ pnbr,
    const __half* __restrict__ Wt, OutT* __restrict__ y,
    float* __restrict__ partials)
{
    extern __shared__ __align__(16) __half smem[];
    const uint32_t sb = smem_u32(smem);

    const int tid  = threadIdx.x;
    const int warp = tid >> 5, lane = tid & 31;
    const int g    = lane >> 2, tig = lane & 3;     // groupID / thread-in-group
    const int rowBase = blockIdx.x * MROWS;
    const int grow = rowBase + tid;                 // one gather row per thread

    const uint32_t Ab[2] = { sb, sb + (uint32_t)A_BUF_H * 2 };
    const uint32_t Bb[2] = { sb + 4 * (uint32_t)A_BUF_H,
                             sb + 4 * (uint32_t)A_BUF_H + (uint32_t)B_BUF_H * 2 };

    float acc[16][4];
#pragma unroll
    for (int n = 0; n < 16; ++n)
#pragma unroll
        for (int j = 0; j < 4; ++j) acc[n][j] = 0.f;

    auto issue = [&](int k, int buf) {
        int pk = (grow < NV) ? pnbr[(size_t)k * NV + grow] : -1;
        const __half* srow = x + (size_t)(pk >= 0 ? pk : 0) * 64;
        int sz = (pk >= 0) ? 16 : 0;                 // zero-fill invalid rows
        uint32_t adst = Ab[buf] + (uint32_t)tid * 144;
#pragma unroll
        for (int i = 0; i < 8; ++i)
            cpa16_cg(adst + i * 16, srow + i * 8, sz);
        const __half* wsrc = Wt + (size_t)k * 4096;
#pragma unroll
        for (int i = 0; i < 4; ++i) {
            int q = tid + 128 * i;                   // 512 x 16B, 8 per 64-row
            cpa16_ca(Bb[buf] + (q >> 3) * 144 + (q & 7) * 16, wsrc + q * 8);
        }
        asm volatile("cp.async.commit_group;" ::: "memory");
    };

    issue(0, 0);

    for (int k = 0; k < KK; ++k) {
        const int buf = k & 1;
        asm volatile("cp.async.wait_group 0;" ::: "memory");   // group k done
        __syncthreads();   // publishes buf; certifies buf^1 reads finished
        if (k + 1 < KK) issue(k + 1, buf ^ 1);                 // async under MMA

        const __half* A = smem + (size_t)buf * A_BUF_H;
        const __half* B = smem + 2 * (size_t)A_BUF_H + (size_t)buf * B_BUF_H;
#pragma unroll
        for (int kc = 0; kc < 4; ++kc) {
            unsigned a[2][4];
#pragma unroll
            for (int mt = 0; mt < 2; ++mt) {
                const int r = warp * 32 + mt * 16 + g;
                a[mt][0] = *reinterpret_cast<const unsigned*>(A + r       * AST + kc * 16 + 2 * tig);
                a[mt][1] = *reinterpret_cast<const unsigned*>(A + (r + 8) * AST + kc * 16 + 2 * tig);
                a[mt][2] = *reinterpret_cast<const unsigned*>(A + r       * AST + kc * 16 + 2 * tig + 8);
                a[mt][3] = *reinterpret_cast<const unsigned*>(A + (r + 8) * AST + kc * 16 + 2 * tig + 8);
            }
#pragma unroll
            for (int n = 0; n < 8; ++n) {
                unsigned b0 = *reinterpret_cast<const unsigned*>(B + (n * 8 + g) * BST + kc * 16 + 2 * tig);
                unsigned b1 = *reinterpret_cast<const unsigned*>(B + (n * 8 + g) * BST + kc * 16 + 2 * tig + 8);
                asm volatile(
                    "mma.sync.aligned.m16n8k16.row.col.f32.f16.f16.f32 "
                    "{%0,%1,%2,%3},{%4,%5,%6,%7},{%8,%9},{%0,%1,%2,%3};\n"
                    : "+f"(acc[n][0]), "+f"(acc[n][1]), "+f"(acc[n][2]), "+f"(acc[n][3])
                    : "r"(a[0][0]), "r"(a[0][1]), "r"(a[0][2]), "r"(a[0][3]), "r"(b0), "r"(b1));
                asm volatile(
                    "mma.sync.aligned.m16n8k16.row.col.f32.f16.f16.f32 "
                    "{%0,%1,%2,%3},{%4,%5,%6,%7},{%8,%9},{%0,%1,%2,%3};\n"
                    : "+f"(acc[8 + n][0]), "+f"(acc[8 + n][1]), "+f"(acc[8 + n][2]), "+f"(acc[8 + n][3])
                    : "r"(a[1][0]), "r"(a[1][1]), "r"(a[1][2]), "r"(a[1][3]), "r"(b0), "r"(b1));
            }
        }
    }

    // ---- epilogue 1: store y (c{0,1}->row g, c{2,3}->row g+8) ----
#pragma unroll
    for (int mt = 0; mt < 2; ++mt) {
        const int r0 = rowBase + warp * 32 + mt * 16 + g;
        const int r1 = r0 + 8;
#pragma unroll
        for (int n = 0; n < 8; ++n) {
            const float* a = acc[mt * 8 + n];
            int col = n * 8 + 2 * tig;
            if constexpr (sizeof(OutT) == 4) {
                if (r0 < NV)
                    *reinterpret_cast<float2*>((float*)y + (size_t)r0 * 64 + col) = make_float2(a[0], a[1]);
                if (r1 < NV)
                    *reinterpret_cast<float2*>((float*)y + (size_t)r1 * 64 + col) = make_float2(a[2], a[3]);
            } else {
                if (r0 < NV)
                    *reinterpret_cast<__half2*>((__half*)y + (size_t)r0 * 64 + col) = __floats2half2_rn(a[0], a[1]);
                if (r1 < NV)
                    *reinterpret_cast<__half2*>((__half*)y + (size_t)r1 * 64 + col) = __floats2half2_rn(a[2], a[3]);
            }
        }
    }

    // ---- epilogue 2: deterministic per-block BN partials from fp32 accs ----
    __syncthreads();                                 // smem free for reuse
    float* smS = reinterpret_cast<float*>(smem);     // [4 warps][64]
    float* smQ = smS + 4 * 64;
#pragma unroll
    for (int n = 0; n < 8; ++n) {
        float s0 = 0.f, s1 = 0.f, q0 = 0.f, q1 = 0.f;
#pragma unroll
        for (int mt = 0; mt < 2; ++mt) {
            const int r0 = rowBase + warp * 32 + mt * 16 + g;
            const float* a = acc[mt * 8 + n];
            if (r0 < NV)     { s0 += a[0]; s1 += a[1]; q0 += a[0]*a[0]; q1 += a[1]*a[1]; }
            if (r0 + 8 < NV) { s0 += a[2]; s1 += a[3]; q0 += a[2]*a[2]; q1 += a[3]*a[3]; }
        }
#pragma unroll
        for (int d = 4; d < 32; d <<= 1) {           // reduce over g lanes
            s0 += __shfl_xor_sync(0xFFFFFFFF, s0, d);
            s1 += __shfl_xor_sync(0xFFFFFFFF, s1, d);
            q0 += __shfl_xor_sync(0xFFFFFFFF, q0, d);
            q1 += __shfl_xor_sync(0xFFFFFFFF, q1, d);
        }
        if (lane < 4) {                              // lane == tig, g == 0
            smS[warp * 64 + n * 8 + 2 * lane]     = s0;
            smS[warp * 64 + n * 8 + 2 * lane + 1] = s1;
            smQ[warp * 64 + n * 8 + 2 * lane]     = q0;
            smQ[warp * 64 + n * 8 + 2 * lane + 1] = q1;
        }
    }
    __syncthreads();
    if (tid < 64) {                                  // fixed-order combine
        float s = smS[tid] + smS[64 + tid] + smS[128 + tid] + smS[192 + tid];
        float q = smQ[tid] + smQ[64 + tid] + smQ[128 + tid] + smQ[192 + tid];
        partials[blockIdx.x * 128 + tid]      = s;
        partials[blockIdx.x * 128 + 64 + tid] = q;
    }
}

// ============================================================================
// One-shot converters / packers
// ============================================================================
__global__ __launch_bounds__(256) void cvt_features_kernel(
    const float4* __restrict__ x, __half2* __restrict__ xh)
{
    long i = (long)blockIdx.x * 256 + threadIdx.x;   // NV*16 float4s, exact
    float4 v = x[i];
    xh[2 * i]     = __floats2half2_rn(v.x, v.y);
    xh[2 * i + 1] = __floats2half2_rn(v.z, v.w);
}

__global__ void cvt_weights_kernel(
    const float* __restrict__ W1, const float* __restrict__ W2,
    __half* __restrict__ Wt)   // [2][27][cout][cin]
{
    int o = blockIdx.x * 256 + threadIdx.x;
    if (o >= 2 * KK * 4096) return;
    int wsel = o / (KK * 4096);
    int rem  = o % (KK * 4096);
    int k = rem >> 12, t = rem & 4095;
    int co = t >> 6, ci = t & 63;
    const float* W = wsel ? W2 : W1;
    Wt[o] = __float2half_rn(W[(size_t)k * 4096 + ci * 64 + co]);
}

__global__ void pack_nbr_kernel(const int* __restrict__ nbr,
                                const float* __restrict__ valid,
                                int* __restrict__ pnbr)
{
    long i = (long)blockIdx.x * 256 + threadIdx.x;
    if (i >= (long)KK * NV) return;
    pnbr[i] = (valid[i] > 0.5f) ? nbr[i] : -1;
}

// ============================================================================
// BN finalize: 1024-thread two-level reduction over NBLK partial rows.
// 8 threads per channel-slot stride the blocks (parallel, MLP-overlapped),
// then a fixed-order SMEM combine -> deterministic.
// ============================================================================
__global__ __launch_bounds__(1024) void finalize_stats_kernel(
    const float* __restrict__ partials, const float* __restrict__ gamma,
    const float* __restrict__ beta, float* __restrict__ ss)
{
    const int tid = threadIdx.x;          // 0..1023
    const int idx = tid & 127;            // channel-slot: 0..63 sum, 64..127 sumsq
    const int r   = tid >> 7;             // 0..7
    float s = 0.f;
    for (int b = r; b < NBLK; b += 8)
        s += partials[(size_t)b * 128 + idx];
    __shared__ float sh[1024];
    __shared__ float tot[128];
    sh[tid] = s;
    __syncthreads();
    if (r == 0) {
        float t = 0.f;
#pragma unroll
        for (int j = 0; j < 8; ++j) t += sh[idx + 128 * j];   // fixed order
        tot[idx] = t;
    }
    __syncthreads();
    if (tid < 64) {
        const float invN = 1.0f / (float)NV;
        float mean  = tot[tid] * invN;
        float var   = tot[64 + tid] * invN - mean * mean;
        float scale = gamma[tid] * rsqrtf(var + 1e-5f);
        ss[tid]      = scale;
        ss[64 + tid] = beta[tid] - mean * scale;
    }
}

// ============================================================================
// Fused BN + ReLU (half, in place) and BN + residual + ReLU (float)
// ============================================================================
__global__ __launch_bounds__(256) void bn_act_half_kernel(
    __half2* __restrict__ y, const float* __restrict__ ss)
{
    long i = (long)blockIdx.x * 256 + threadIdx.x;   // NV*32 half2s, exact
    const int cb = (int)(i & 31);
    float2 f = __half22float2(y[i]);
    float rx = fmaf(f.x, ss[2 * cb],     ss[64 + 2 * cb]);
    float ry = fmaf(f.y, ss[2 * cb + 1], ss[64 + 2 * cb + 1]);
    y[i] = __floats2half2_rn(fmaxf(rx, 0.f), fmaxf(ry, 0.f));
}

__global__ __launch_bounds__(256) void bn_act_float_kernel(
    float* __restrict__ y, const float* __restrict__ ss,
    const float* __restrict__ residual)
{
    long i = (long)blockIdx.x * 256 + threadIdx.x;   // NV*16 float4s, exact
    float4 v = reinterpret_cast<float4*>(y)[i];
    const int cb = (int)(i & 15);
    float4 sc = reinterpret_cast<const float4*>(ss)[cb];
    float4 sh = reinterpret_cast<const float4*>(ss + 64)[cb];
    float4 f = reinterpret_cast<const float4*>(residual)[i];
    float4 r;
    r.x = fmaxf(fmaf(v.x, sc.x, sh.x) + f.x, 0.f);
    r.y = fmaxf(fmaf(v.y, sc.y, sh.y) + f.y, 0.f);
    r.z = fmaxf(fmaf(v.z, sc.z, sh.z) + f.z, 0.f);
    r.w = fmaxf(fmaf(v.w, sc.w, sh.w) + f.w, 0.f);
    reinterpret_cast<float4*>(y)[i] = r;
}

// ============================================================================
// kernel_launch
// ============================================================================
extern "C" void kernel_launch(void* const* d_in, const int* in_sizes, int n_in,
                              void* d_out, int out_size)
{
    const float* features = (const float*)d_in[0];
    const int*   nbr      = (const int*)  d_in[1];
    const float* valid    = (const float*)d_in[2];
    const float* W1       = (const float*)d_in[3];
    const float* gamma1   = (const float*)d_in[4];
    const float* beta1    = (const float*)d_in[5];
    const float* W2       = (const float*)d_in[6];
    const float* gamma2   = (const float*)d_in[7];
    const float* beta2    = (const float*)d_in[8];
    float* out = (float*)d_out;

    __half *xh, *y1h, *Wt;
    int* pnbr;
    float *partials, *ss1, *ss2;
    cudaGetSymbolAddress((void**)&xh,       g_xh);
    cudaGetSymbolAddress((void**)&y1h,      g_y1h);
    cudaGetSymbolAddress((void**)&Wt,       g_Wt);
    cudaGetSymbolAddress((void**)&pnbr,     g_pnbr);
    cudaGetSymbolAddress((void**)&partials, g_partials);
    cudaGetSymbolAddress((void**)&ss1,      g_ss1);
    cudaGetSymbolAddress((void**)&ss2,      g_ss2);

    cudaFuncSetAttribute(conv_kernel<__half>, cudaFuncAttributeMaxDynamicSharedMemorySize, SMEM_TOTAL);
    cudaFuncSetAttribute(conv_kernel<float>,  cudaFuncAttributeMaxDynamicSharedMemorySize, SMEM_TOTAL);

    const int cvtBlocks  = (int)(((long)NV * 16) / 256);       // 31250, exact
    const int bnHBlocks  = (int)(((long)NV * 32) / 256);       // 62500, exact
    const int wBlocks    = (2 * KK * 4096 + 255) / 256;
    const int pkBlocks   = (int)(((long)KK * NV + 255) / 256);

    cvt_features_kernel<<<cvtBlocks, 256>>>((const float4*)features, (__half2*)xh);
    cvt_weights_kernel<<<wBlocks, 256>>>(W1, W2, Wt);
    pack_nbr_kernel<<<pkBlocks, 256>>>(nbr, valid, pnbr);

    conv_kernel<__half><<<NBLK, 128, SMEM_TOTAL>>>(xh, pnbr, Wt, y1h, partials);
    finalize_stats_kernel<<<1, 1024>>>(partials, gamma1, beta1, ss1);
    bn_act_half_kernel<<<bnHBlocks, 256>>>((__half2*)y1h, ss1);

    conv_kernel<float><<<NBLK, 128, SMEM_TOTAL>>>(y1h, pnbr, Wt + (size_t)KK * 4096, out, partials);
    finalize_stats_kernel<<<1, 1024>>>(partials, gamma2, beta2, ss2);
    bn_act_float_kernel<<<cvtBlocks, 256>>>(out, ss2, features);
}